// round 1
// baseline (speedup 1.0000x reference)
#include <cuda_runtime.h>
#include <math.h>

// Problem constants
constexpr int kV = 50257;
constexpr int kH = 512;
constexpr int kS = 512;
constexpr int kB = 8;
constexpr int kT = 64;
constexpr int kM = kT * kB;  // 512 rows (t*B+b)

// Scratch (device globals — allocation-free per harness rules)
__device__ float g_logits[(size_t)kM * kV];   // ~103 MB
__device__ float g_prob[kM];
__device__ float g_rowmax[kM];
__device__ float g_rowsum[kM];
__device__ float g_zc[kM];
__device__ int   g_leader[kB * kS];

// ---------------- packed f32x2 helpers (sm_103a) ----------------
__device__ __forceinline__ unsigned long long pack2(float x, float y) {
    unsigned long long r;
    asm("mov.b64 %0, {%1, %2};" : "=l"(r) : "f"(x), "f"(y));
    return r;
}
__device__ __forceinline__ void unpack2(unsigned long long v, float& x, float& y) {
    asm("mov.b64 {%0, %1}, %2;" : "=f"(x), "=f"(y) : "l"(v));
}
__device__ __forceinline__ unsigned long long fma2(unsigned long long a,
                                                   unsigned long long b,
                                                   unsigned long long c) {
    unsigned long long d;
    asm("fma.rn.f32x2 %0, %1, %2, %3;" : "=l"(d) : "l"(a), "l"(b), "l"(c));
    return d;
}

// ---------------- K1: context + p_gen ----------------
// context[t,b,h] = sum_s attn[b,t,s] * memory[s,b,h]; p = sigmoid(ctx . W_prob + b_prob)
__global__ void k_prob(const float* __restrict__ attn, const float* __restrict__ mem,
                       const float* __restrict__ Wp, const float* __restrict__ bp) {
    int m = blockIdx.x;
    int t = m / kB, b = m % kB;
    __shared__ float a_sh[kS];
    int h = threadIdx.x;  // 512 threads
    a_sh[h] = attn[((size_t)b * kT + t) * kS + h];
    __syncthreads();
    const float* mp = mem + (size_t)b * kH + h;
    float ctx = 0.f;
#pragma unroll 8
    for (int s = 0; s < kS; s++)
        ctx = fmaf(a_sh[s], mp[(size_t)s * kB * kH], ctx);
    __shared__ float red[kS];
    red[h] = ctx * Wp[h];
    __syncthreads();
    for (int off = kS / 2; off > 0; off >>= 1) {
        if (h < off) red[h] += red[h + off];
        __syncthreads();
    }
    if (h == 0) {
        float z = red[0] + bp[0];
        g_prob[m] = 1.f / (1.f + expf(-z));
    }
}

// ---------------- P0: leader flags (first occurrence of token per batch col) ----------------
__global__ void k_leader(const int* __restrict__ src) {
    int b = blockIdx.x;
    int s = threadIdx.x;
    __shared__ int tok[kS];
    tok[s] = src[(size_t)s * kB + b];
    __syncthreads();
    int me = tok[s];
    int lead = 1;
    for (int j = 0; j < s; j++)
        if (tok[j] == me) { lead = 0; break; }
    g_leader[b * kS + s] = lead;
}

// ---------------- K2: copy-softmax denominator Z_c per (t,b) ----------------
// Z_c = (V - U_b) * exp(0) + sum over unique tokens exp(group-summed attn)
__global__ void k_zc(const int* __restrict__ src, const float* __restrict__ attn) {
    int m = blockIdx.x;
    int t = m / kB, b = m % kB;
    __shared__ float a_sh[kS];
    __shared__ int tok[kS];
    int s = threadIdx.x;
    a_sh[s] = attn[((size_t)b * kT + t) * kS + s];
    tok[s] = src[(size_t)s * kB + b];
    __syncthreads();
    float val = 0.f, cnt = 0.f;
    if (g_leader[b * kS + s]) {
        float c = 0.f;
        int me = tok[s];
        for (int j = 0; j < kS; j++)
            if (tok[j] == me) c += a_sh[j];
        val = expf(c);
        cnt = 1.f;
    }
    __shared__ float r1[kS], r2[kS];
    r1[s] = val; r2[s] = cnt;
    __syncthreads();
    for (int off = kS / 2; off > 0; off >>= 1) {
        if (s < off) { r1[s] += r1[s + off]; r2[s] += r2[s + off]; }
        __syncthreads();
    }
    if (s == 0) g_zc[m] = ((float)kV - r2[0]) + r1[0];
}

// ---------------- K3: GEMM logits = decode_output @ W_gen + b_gen ----------------
// M=512, K=512, N=50257. fp32 with packed f32x2 FMA. 128x128x16 tiles, 256 threads,
// micro-tile 8(m) x 4(pairs of n) per thread.
constexpr int BM = 128, BN = 128, BK = 16;

__global__ void __launch_bounds__(256) k_gemm(const float* __restrict__ A,
                                              const float* __restrict__ Bw,
                                              const float* __restrict__ bias) {
    __shared__ __align__(16) float As[BM][BK];      // m-major, conflict-free
    __shared__ __align__(16) float Bs[BK][BN];
    int tid = threadIdx.x;
    int tx = tid & 15, ty = tid >> 4;
    int m0 = blockIdx.x * BM;                       // x = m-tile (4) -> consecutive blocks share B tile
    int n0 = blockIdx.y * BN;

    unsigned long long acc[8][4];
#pragma unroll
    for (int i = 0; i < 8; i++)
#pragma unroll
        for (int j = 0; j < 4; j++) acc[i][j] = 0ull;

    for (int k0 = 0; k0 < kH; k0 += BK) {
        // Load A tile: 2048 floats = 512 float4, 2 per thread (H=512 -> 16B aligned)
#pragma unroll
        for (int i = 0; i < 2; i++) {
            int f = tid + i * 256;
            int r = f >> 2;
            int q = f & 3;
            float4 v = *(const float4*)(A + (size_t)(m0 + r) * kH + k0 + q * 4);
            *(float4*)&As[r][q * 4] = v;
        }
        // Load B tile: scalar (V odd -> no vector alignment), coalesced, guarded
#pragma unroll
        for (int i = 0; i < 8; i++) {
            int f = tid + i * 256;
            int r = f >> 7;
            int c = f & 127;
            int n = n0 + c;
            Bs[r][c] = (n < kV) ? Bw[(size_t)(k0 + r) * kV + n] : 0.0f;
        }
        __syncthreads();
#pragma unroll
        for (int kk = 0; kk < BK; kk++) {
            unsigned long long rn2[4];
            const unsigned long long* brow = (const unsigned long long*)Bs[kk];
#pragma unroll
            for (int j = 0; j < 4; j++) rn2[j] = brow[j * 16 + tx];
#pragma unroll
            for (int i = 0; i < 8; i++) {
                float rv = As[i * 16 + ty][kk];
                unsigned long long rm2 = pack2(rv, rv);
#pragma unroll
                for (int j = 0; j < 4; j++) acc[i][j] = fma2(rm2, rn2[j], acc[i][j]);
            }
        }
        __syncthreads();
    }
    // Epilogue: n = n0 + j*32 + tx*2 (+1)
#pragma unroll
    for (int i = 0; i < 8; i++) {
        int m = m0 + i * 16 + ty;
        float* orow = g_logits + (size_t)m * kV;
#pragma unroll
        for (int j = 0; j < 4; j++) {
            int n = n0 + j * 32 + tx * 2;
            float lo, hi;
            unpack2(acc[i][j], lo, hi);
            if (n < kV)     orow[n]     = lo + bias[n];
            if (n + 1 < kV) orow[n + 1] = hi + bias[n + 1];
        }
    }
}

// ---------------- K4: row max + sumexp over V (online) ----------------
__global__ void k_rowstats() {
    int m = blockIdx.x;
    const float* row = g_logits + (size_t)m * kV;
    int tid = threadIdx.x;
    float mx = -INFINITY, sm = 0.f;
    for (int v = tid; v < kV; v += 256) {
        float g = row[v];
        if (g > mx) { sm = sm * __expf(mx - g) + 1.f; mx = g; }
        else        { sm += __expf(g - mx); }
    }
    __shared__ float smax[256], ssum[256];
    smax[tid] = mx; ssum[tid] = sm;
    __syncthreads();
    for (int off = 128; off > 0; off >>= 1) {
        if (tid < off) {
            float m2 = smax[tid + off], s2 = ssum[tid + off];
            float mxl = smax[tid], sml = ssum[tid];
            if (m2 > mxl) { sml = sml * __expf(mxl - m2) + s2; mxl = m2; }
            else          { sml += s2 * __expf(m2 - mxl); }
            smax[tid] = mxl; ssum[tid] = sml;
        }
        __syncthreads();
    }
    if (tid == 0) { g_rowmax[m] = smax[0]; g_rowsum[m] = ssum[0]; }
}

// ---------------- K5: dense output with c_v = 0 closed form ----------------
__global__ void k_out(float* __restrict__ out) {
    int m = blockIdx.y;
    int v = blockIdx.x * 256 + threadIdx.x;
    if (v >= kV) return;
    float p = g_prob[m];
    float sgen = p / g_rowsum[m];
    float mx = g_rowmax[m];
    float scopy = (1.f - p) / g_zc[m];
    float g = g_logits[(size_t)m * kV + v];
    out[(size_t)m * kV + v] = logf(fmaf(sgen, __expf(g - mx), scopy));
}

// ---------------- K6: sparse fixup for touched vocab slots ----------------
__global__ void k_fix(const int* __restrict__ src, const float* __restrict__ attn,
                      float* __restrict__ out) {
    int m = blockIdx.x;
    int t = m / kB, b = m % kB;
    __shared__ float a_sh[kS];
    __shared__ int tok[kS];
    int s = threadIdx.x;
    a_sh[s] = attn[((size_t)b * kT + t) * kS + s];
    tok[s] = src[(size_t)s * kB + b];
    __syncthreads();
    if (!g_leader[b * kS + s]) return;
    int vv = tok[s];
    float c = 0.f;
    for (int j = 0; j < kS; j++)
        if (tok[j] == vv) c += a_sh[j];
    float p = g_prob[m];
    float sgen = p / g_rowsum[m];
    float mx = g_rowmax[m];
    float scopy = (1.f - p) / g_zc[m];
    float g = g_logits[(size_t)m * kV + vv];
    out[(size_t)m * kV + vv] = logf(fmaf(sgen, __expf(g - mx), scopy * expf(c)));
}

extern "C" void kernel_launch(void* const* d_in, const int* in_sizes, int n_in,
                              void* d_out, int out_size) {
    const int*   src  = (const int*)d_in[0];    // src_full [S,B] int32
    const float* dec  = (const float*)d_in[1];  // decode_output [T,B,H]
    const float* attn = (const float*)d_in[2];  // decode_attn [B,T,S]
    const float* mem  = (const float*)d_in[3];  // memory [S,B,H]
    const float* Wg   = (const float*)d_in[4];  // W_gen [H,V]
    const float* bg   = (const float*)d_in[5];  // b_gen [V]
    const float* Wp   = (const float*)d_in[6];  // W_prob [H]
    const float* bp   = (const float*)d_in[7];  // b_prob [1]
    float* out = (float*)d_out;                 // [T,B,V] f32

    k_leader<<<kB, kS>>>(src);
    k_prob<<<kM, kS>>>(attn, mem, Wp, bp);
    k_zc<<<kM, kS>>>(src, attn);
    k_gemm<<<dim3(kM / BM, (kV + BN - 1) / BN), 256>>>(dec, Wg, bg);
    k_rowstats<<<kM, 256>>>();
    k_out<<<dim3((kV + 255) / 256, kM), 256>>>(out);
    k_fix<<<kM, kS>>>(src, attn, out);
}

// round 3
// speedup vs baseline: 2.3175x; 2.3175x over previous
#include <cuda_runtime.h>
#include <math.h>
#include <stdint.h>

// Problem constants
constexpr int kV = 50257;
constexpr int kH = 512;
constexpr int kS = 512;
constexpr int kB = 8;
constexpr int kT = 64;
constexpr int kM = kT * kB;          // 512 rows (t*B+b)
constexpr int NYB = 393;             // n-tiles of 128 -> 393*128 = 50304
constexpr int kVP = NYB * 128;       // padded vocab stride (50304, 16B-aligned rows)

// Scratch (device globals — allocation-free per harness rules)
__device__ float g_logits[(size_t)kM * kV];      // ~103 MB
__device__ float g_Bp[(size_t)kH * kVP];         // padded tf32 W_gen ~103 MB
__device__ float g_At[kH * kM];                  // transposed tf32 A (k-major)
__device__ float g_pmax[(size_t)NYB * kM];
__device__ float g_psum[(size_t)NYB * kM];
__device__ float g_prob[kM];
__device__ float g_rowmax[kM];
__device__ float g_rowsum[kM];
__device__ float g_zc[kM];
__device__ float g_q[kS * kB];
__device__ int   g_leader[kB * kS];

// ======================= helpers =======================
__device__ __forceinline__ float to_tf32(float x) {
    float r;
    asm("cvt.rna.tf32.f32 %0, %1;" : "=f"(r) : "f"(x));
    return r;
}
__device__ __forceinline__ uint32_t smem_u32(const void* p) {
    uint32_t a;
    asm("{ .reg .u64 t; cvta.to.shared.u64 t, %1; cvt.u32.u64 %0, t; }" : "=r"(a) : "l"(p));
    return a;
}
#define CP16(dst, src) \
    asm volatile("cp.async.cg.shared.global [%0], [%1], 16;" :: "r"(dst), "l"(src))
#define CPCOMMIT() asm volatile("cp.async.commit_group;" ::: "memory")
#define CPWAIT2()  asm volatile("cp.async.wait_group 2;" ::: "memory")

__device__ __forceinline__ void mma_tf32(float* c, const uint32_t* a, const uint32_t* b) {
    asm volatile(
        "mma.sync.aligned.m16n8k8.row.col.f32.tf32.tf32.f32 "
        "{%0,%1,%2,%3}, {%4,%5,%6,%7}, {%8,%9}, {%0,%1,%2,%3};"
        : "+f"(c[0]), "+f"(c[1]), "+f"(c[2]), "+f"(c[3])
        : "r"(a[0]), "r"(a[1]), "r"(a[2]), "r"(a[3]), "r"(b[0]), "r"(b[1]));
}

// ======================= pre-pass: A transpose (tf32) =======================
__global__ void k_at(const float* __restrict__ A) {
    __shared__ float t[32][33];
    int bx = blockIdx.x * 32, by = blockIdx.y * 32;  // bx: k, by: m
    int tx = threadIdx.x, ty = threadIdx.y;          // 32 x 8
#pragma unroll
    for (int i = 0; i < 4; i++)
        t[ty + 8 * i][tx] = A[(size_t)(by + ty + 8 * i) * kH + bx + tx];
    __syncthreads();
#pragma unroll
    for (int i = 0; i < 4; i++)
        g_At[(size_t)(bx + ty + 8 * i) * kM + by + tx] = to_tf32(t[tx][ty + 8 * i]);
}

// ======================= pre-pass: padded tf32 copy of W_gen =======================
constexpr int BCHUNK = 8192;
__global__ void __launch_bounds__(256) k_bpad(const float* __restrict__ Bw) {
    __shared__ float sb[BCHUNK + 16];
    int k = blockIdx.y;
    int cbase = blockIdx.x * BCHUNK;
    size_t rowbase = (size_t)k * kV;
    int phi = (int)((rowbase + cbase) & 3);
    size_t astart = (rowbase + cbase) - phi;            // 16B-aligned element index
    const size_t total = (size_t)kH * kV;
    for (int i = threadIdx.x; i < BCHUNK / 4 + 1; i += 256) {
        size_t src = astart + (size_t)i * 4;
        float4 v = (src < total) ? *(const float4*)(Bw + src) : make_float4(0, 0, 0, 0);
        *(float4*)(sb + i * 4) = v;
    }
    __syncthreads();
    size_t drow = (size_t)k * kVP;
    for (int i = threadIdx.x; i < BCHUNK / 4; i += 256) {
        int j = cbase + i * 4;
        if (j >= kVP) break;
        float4 v;
        v.x = (j + 0 < kV) ? to_tf32(sb[phi + i * 4 + 0]) : 0.f;
        v.y = (j + 1 < kV) ? to_tf32(sb[phi + i * 4 + 1]) : 0.f;
        v.z = (j + 2 < kV) ? to_tf32(sb[phi + i * 4 + 2]) : 0.f;
        v.w = (j + 3 < kV) ? to_tf32(sb[phi + i * 4 + 3]) : 0.f;
        *(float4*)(g_Bp + drow + j) = v;
    }
}

// ======================= GEMM: logits = A @ W + bias (mma.sync tf32) =======================
constexpr int BM = 128, BN = 128, KC = 32;
constexpr int NST = 3;
constexpr int NKT = kH / KC;              // 16 k-tiles
constexpr int TSTR = 136;                 // smem row stride in floats (128 + 8)
constexpr int A_FLTS = KC * TSTR;         // 4352
constexpr int STAGE_FLTS = 2 * A_FLTS;    // 8704
constexpr int GEMM_SMEM = NST * STAGE_FLTS * 4;  // 104448 B

__global__ void __launch_bounds__(256, 1)
k_gemm(const float* __restrict__ bias) {
    extern __shared__ float sm[];
    const int tid = threadIdx.x;
    const int lane = tid & 31, wid = tid >> 5;
    const int wm = wid & 1, wn = wid >> 1;      // 2 x 4 warp grid
    const int g = lane >> 2, l4 = lane & 3;
    const int m0 = blockIdx.x * BM, n0 = blockIdx.y * BN;
    const uint32_t sbase = smem_u32(sm);

    float acc[4][4][4];
#pragma unroll
    for (int i = 0; i < 4; i++)
#pragma unroll
        for (int j = 0; j < 4; j++)
#pragma unroll
            for (int q = 0; q < 4; q++) acc[i][j][q] = 0.f;

    auto load_tile = [&](int c, int s) {
        uint32_t sa = sbase + s * STAGE_FLTS * 4;
        uint32_t sbb = sa + A_FLTS * 4;
#pragma unroll
        for (int i = 0; i < 4; i++) {
            int idx = tid + i * 256;            // 1024 granules
            int k = idx >> 5, q = idx & 31;
            CP16(sa + (k * TSTR + q * 4) * 4, g_At + (size_t)(c * KC + k) * kM + m0 + q * 4);
        }
#pragma unroll
        for (int i = 0; i < 4; i++) {
            int idx = tid + i * 256;
            int k = idx >> 5, q = idx & 31;
            CP16(sbb + (k * TSTR + q * 4) * 4, g_Bp + (size_t)(c * KC + k) * kVP + n0 + q * 4);
        }
    };

#pragma unroll
    for (int s = 0; s < NST; s++) { load_tile(s, s); CPCOMMIT(); }

#pragma unroll 1
    for (int kt = 0; kt < NKT; kt++) {
        int s = kt % NST;
        CPWAIT2();
        __syncthreads();
        const float* As = sm + s * STAGE_FLTS;
        const float* Bs = As + A_FLTS;
#pragma unroll
        for (int ks = 0; ks < 4; ks++) {
            int k0 = ks * 8;
            uint32_t a[4][4], b[4][2];
#pragma unroll
            for (int mf = 0; mf < 4; mf++) {
                int m = wm * 64 + mf * 16 + g;
                const float* ap = As + (k0 + l4) * TSTR + m;
                a[mf][0] = __float_as_uint(ap[0]);
                a[mf][1] = __float_as_uint(ap[8]);
                a[mf][2] = __float_as_uint(ap[4 * TSTR]);
                a[mf][3] = __float_as_uint(ap[4 * TSTR + 8]);
            }
#pragma unroll
            for (int nf = 0; nf < 4; nf++) {
                int n = wn * 32 + nf * 8 + g;
                const float* bp = Bs + (k0 + l4) * TSTR + n;
                b[nf][0] = __float_as_uint(bp[0]);
                b[nf][1] = __float_as_uint(bp[4 * TSTR]);
            }
#pragma unroll
            for (int mf = 0; mf < 4; mf++)
#pragma unroll
                for (int nf = 0; nf < 4; nf++)
                    mma_tf32(acc[mf][nf], a[mf], b[nf]);
        }
        __syncthreads();
        if (kt + NST < NKT) load_tile(kt + NST, s);
        CPCOMMIT();
    }
    __syncthreads();

    // ---------- epilogue: bias + store + per-(row, n-tile) partial stats ----------
    float* s_m = sm;           // [128][4]
    float* s_s = sm + 512;
    float bv[4][2];
#pragma unroll
    for (int nf = 0; nf < 4; nf++) {
        int n = n0 + wn * 32 + nf * 8 + l4 * 2;
        bv[nf][0] = (n < kV) ? __ldg(bias + n) : 0.f;
        bv[nf][1] = (n + 1 < kV) ? __ldg(bias + n + 1) : 0.f;
    }
#pragma unroll
    for (int mf = 0; mf < 4; mf++) {
#pragma unroll
        for (int h = 0; h < 2; h++) {
            int rowb = wm * 64 + mf * 16 + g + h * 8;
            size_t rbase = (size_t)(m0 + rowb) * kV;
            float vv[8];
            float mx = -INFINITY;
#pragma unroll
            for (int nf = 0; nf < 4; nf++) {
                int n = n0 + wn * 32 + nf * 8 + l4 * 2;
                float x0 = acc[mf][nf][h * 2 + 0] + bv[nf][0];
                float x1 = acc[mf][nf][h * 2 + 1] + bv[nf][1];
                if (n < kV)     { g_logits[rbase + n] = x0;     mx = fmaxf(mx, x0); }
                else x0 = -INFINITY;
                if (n + 1 < kV) { g_logits[rbase + n + 1] = x1; mx = fmaxf(mx, x1); }
                else x1 = -INFINITY;
                vv[nf * 2] = x0; vv[nf * 2 + 1] = x1;
            }
            mx = fmaxf(mx, __shfl_xor_sync(0xffffffffu, mx, 1));
            mx = fmaxf(mx, __shfl_xor_sync(0xffffffffu, mx, 2));
            float sum = 0.f;
            if (mx > -INFINITY) {
#pragma unroll
                for (int j = 0; j < 8; j++) sum += __expf(vv[j] - mx);
            }
            sum += __shfl_xor_sync(0xffffffffu, sum, 1);
            sum += __shfl_xor_sync(0xffffffffu, sum, 2);
            if (l4 == 0) { s_m[rowb * 4 + wn] = mx; s_s[rowb * 4 + wn] = sum; }
        }
    }
    __syncthreads();
    if (tid < 128) {
        float mx = -INFINITY, sum = 0.f;
#pragma unroll
        for (int w = 0; w < 4; w++) {
            float m2 = s_m[tid * 4 + w], s2 = s_s[tid * 4 + w];
            if (m2 > mx) { sum = sum * __expf(mx - m2) + s2; mx = m2; }
            else         { sum += s2 * __expf(m2 - mx); }
        }
        g_pmax[(size_t)blockIdx.y * kM + m0 + tid] = mx;
        g_psum[(size_t)blockIdx.y * kM + m0 + tid] = sum;
    }
}

// ======================= final row-stats reduce =======================
__global__ void k_rowfin() {
    int row = blockIdx.x;        // 512 rows, 1 warp each
    int lane = threadIdx.x;
    float mx = -INFINITY, sum = 0.f;
    for (int y = lane; y < NYB; y += 32) {
        float m2 = g_pmax[(size_t)y * kM + row], s2 = g_psum[(size_t)y * kM + row];
        if (m2 > mx) { sum = sum * __expf(mx - m2) + s2; mx = m2; }
        else         { sum += s2 * __expf(m2 - mx); }
    }
#pragma unroll
    for (int o = 16; o > 0; o >>= 1) {
        float m2 = __shfl_xor_sync(0xffffffffu, mx, o);
        float s2 = __shfl_xor_sync(0xffffffffu, sum, o);
        if (m2 > mx) { sum = sum * __expf(mx - m2) + s2; mx = m2; }
        else         { sum += s2 * __expf(m2 - mx); }
    }
    if (lane == 0) { g_rowmax[row] = mx; g_rowsum[row] = sum; }
}

// ======================= q[s,b] = memory[s,b,:] . W_prob =======================
__global__ void k_q(const float* __restrict__ mem, const float* __restrict__ Wp) {
    int row = blockIdx.x * 4 + (threadIdx.x >> 5);
    int lane = threadIdx.x & 31;
    const float* r = mem + (size_t)row * kH;
    float acc = 0.f;
#pragma unroll 4
    for (int h = lane; h < kH; h += 32) acc = fmaf(r[h], Wp[h], acc);
#pragma unroll
    for (int o = 16; o > 0; o >>= 1) acc += __shfl_down_sync(0xffffffffu, acc, o);
    if (lane == 0) g_q[row] = acc;
}

// ======================= leader flags =======================
__global__ void k_leader(const int* __restrict__ src) {
    int b = blockIdx.x;
    int s = threadIdx.x;
    __shared__ int tok[kS];
    tok[s] = src[(size_t)s * kB + b];
    __syncthreads();
    int me = tok[s];
    int lead = 1;
    for (int j = 0; j < s; j++)
        if (tok[j] == me) { lead = 0; break; }
    g_leader[b * kS + s] = lead;
}

// ======================= Z_c + p_gen per (t,b) =======================
__global__ void k_zc(const int* __restrict__ src, const float* __restrict__ attn,
                     const float* __restrict__ bp) {
    int m = blockIdx.x;
    int t = m / kB, b = m % kB;
    __shared__ float a_sh[kS];
    __shared__ int tok[kS];
    __shared__ float r1[kS], r2[kS], r3[kS];
    int s = threadIdx.x;
    float av = attn[((size_t)b * kT + t) * kS + s];
    a_sh[s] = av;
    tok[s] = src[(size_t)s * kB + b];
    r3[s] = av * g_q[s * kB + b];
    __syncthreads();
    float val = 0.f, cnt = 0.f;
    if (g_leader[b * kS + s]) {
        float c = 0.f;
        int me = tok[s];
        for (int j = 0; j < kS; j++)
            if (tok[j] == me) c += a_sh[j];
        val = expf(c);
        cnt = 1.f;
    }
    r1[s] = val; r2[s] = cnt;
    __syncthreads();
    for (int off = kS / 2; off > 0; off >>= 1) {
        if (s < off) { r1[s] += r1[s + off]; r2[s] += r2[s + off]; r3[s] += r3[s + off]; }
        __syncthreads();
    }
    if (s == 0) {
        g_zc[m] = ((float)kV - r2[0]) + r1[0];
        float z = r3[0] + bp[0];
        g_prob[m] = 1.f / (1.f + expf(-z));
    }
}

// ======================= single-pass dense output =======================
__global__ void k_logmix(float* __restrict__ out) {
    int m = blockIdx.y;
    int v = blockIdx.x * 256 + threadIdx.x;
    if (v >= kV) return;
    float p = g_prob[m];
    float sgen = p / g_rowsum[m];
    float mxv = g_rowmax[m];
    float scopy = (1.f - p) / g_zc[m];
    float gl = g_logits[(size_t)m * kV + v];
    out[(size_t)m * kV + v] = logf(fmaf(sgen, __expf(gl - mxv), scopy));
}

// ======================= sparse copy fixup =======================
__global__ void k_fix(const int* __restrict__ src, const float* __restrict__ attn,
                      float* __restrict__ out) {
    int m = blockIdx.x;
    int t = m / kB, b = m % kB;
    __shared__ float a_sh[kS];
    __shared__ int tok[kS];
    int s = threadIdx.x;
    a_sh[s] = attn[((size_t)b * kT + t) * kS + s];
    tok[s] = src[(size_t)s * kB + b];
    __syncthreads();
    if (!g_leader[b * kS + s]) return;
    int vv = tok[s];
    float c = 0.f;
    for (int j = 0; j < kS; j++)
        if (tok[j] == vv) c += a_sh[j];
    float p = g_prob[m];
    float sgen = p / g_rowsum[m];
    float mxv = g_rowmax[m];
    float scopy = (1.f - p) / g_zc[m];
    float gl = g_logits[(size_t)m * kV + vv];
    out[(size_t)m * kV + vv] = logf(fmaf(sgen, __expf(gl - mxv), scopy * expf(c)));
}

extern "C" void kernel_launch(void* const* d_in, const int* in_sizes, int n_in,
                              void* d_out, int out_size) {
    const int*   src  = (const int*)d_in[0];    // src_full [S,B] int32
    const float* dec  = (const float*)d_in[1];  // decode_output [T,B,H]
    const float* attn = (const float*)d_in[2];  // decode_attn [B,T,S]
    const float* mem  = (const float*)d_in[3];  // memory [S,B,H]
    const float* Wg   = (const float*)d_in[4];  // W_gen [H,V]
    const float* bg   = (const float*)d_in[5];  // b_gen [V]
    const float* Wp   = (const float*)d_in[6];  // W_prob [H]
    const float* bp   = (const float*)d_in[7];  // b_prob [1]
    float* out = (float*)d_out;                 // [T,B,V] f32

    cudaFuncSetAttribute(k_gemm, cudaFuncAttributeMaxDynamicSharedMemorySize, GEMM_SMEM);

    k_bpad<<<dim3((kVP + BCHUNK - 1) / BCHUNK, kH), 256>>>(Wg);
    k_at<<<dim3(16, 16), dim3(32, 8)>>>(dec);
    k_leader<<<kB, kS>>>(src);
    k_q<<<(kS * kB) / 4, 128>>>(mem, Wp);
    k_zc<<<kM, kS>>>(src, attn, bp);
    k_gemm<<<dim3(kM / BM, NYB), 256, GEMM_SMEM>>>(bg);
    k_rowfin<<<kM, 32>>>();
    k_logmix<<<dim3((kV + 255) / 256, kM), 256>>>(out);
    k_fix<<<kM, kS>>>(src, attn, out);
}